// round 4
// baseline (speedup 1.0000x reference)
#include <cuda_runtime.h>
#include <cuda_bf16.h>
#include <cstdint>

using ull = unsigned long long;

__device__ __forceinline__ ull pk(float lo, float hi) {
  ull r; asm("mov.b64 %0, {%1,%2};" : "=l"(r) : "f"(lo), "f"(hi)); return r;
}
__device__ __forceinline__ void upk(ull v, float& lo, float& hi) {
  asm("mov.b64 {%0,%1}, %2;" : "=f"(lo), "=f"(hi) : "l"(v));
}
__device__ __forceinline__ ull ffma2(ull a, ull b, ull c) {
  ull d; asm("fma.rn.f32x2 %0, %1, %2, %3;" : "=l"(d) : "l"(a), "l"(b), "l"(c)); return d;
}

// Scalar complex MAC: (sr,si) += (ar,ai)*(br,bi)
#define CMAC(sr, si, ar, ai, br, bi) do { \
  (sr) = fmaf((ar), (br), (sr)); (sr) = fmaf(-(ai), (bi), (sr)); \
  (si) = fmaf((ar), (bi), (si)); (si) = fmaf((ai), (br), (si)); } while (0)

constexpr int Lc = 2048;
constexpr int T = 32;                   // steps per chunk
constexpr int NCHUNK = Lc / T;          // 64
constexpr int NSEQ = 256;               // B*C
constexpr int NUNIT = NSEQ * NCHUNK;    // 16384

__device__ float2 g_M2[NUNIT * 64];     // chunk transition matrices (row-major)
__device__ float2 g_v2[NUNIT * 8];      // chunk offsets
__device__ float2 g_E2[NUNIT * 8];      // entering states

// SMEM layout (bank-conflict-free): row stride 144 B (8 ull2 + 16B pad),
// unit stride 8*144+16 = 1168 B (≡16 mod 128 → the 4 units of a warp land on
// distinct banks for the broadcast reads).
constexpr int SA_ROW  = 144;
constexpr int SA_UNIT = SA_ROW * 8 + 16;   // 1168
constexpr int SV_UNIT = 144;               // 8 ull2 + pad

// ---------------------------------------------------------------------------
// Kernel 1: fold each chunk of T steps into (M, v): s_out = M s_in + v.
// 8 threads per unit; thread j owns column j of M. A is staged in SMEM as
// packed f32x2 pair forms: p1=(ar,ar), p2=(-ai,ai) per element, so each
// complex MAC is 2 packed FMAs.
// ---------------------------------------------------------------------------
__global__ __launch_bounds__(256) void k_fold(
    const float* __restrict__ Are, const float* __restrict__ Aim,
    const float* __restrict__ Xre, const float* __restrict__ Xim)
{
  __shared__ __align__(16) char sAbuf[32 * SA_UNIT];
  __shared__ __align__(16) char sVbuf[32 * SV_UNIT];

  const int tid = threadIdx.x;
  const int u = tid >> 3, j = tid & 7;
  const int unit = blockIdx.x * 32 + u;
  const int seq = unit >> 6, chunk = unit & (NCHUNK - 1);
  const int b = seq >> 6, c = seq & 63;
  const int t0 = chunk * T;

  const float* arp = Are + (size_t)(b * Lc + t0) * 4096 + c * 64 + j * 8;
  const float* aip = Aim + (size_t)(b * Lc + t0) * 4096 + c * 64 + j * 8;
  const float* xrp = Xre + (size_t)(b * Lc + t0) * 512 + c * 8 + j;
  const float* xip = Xim + (size_t)(b * Lc + t0) * 512 + c * 8 + j;

  char* sA = sAbuf + u * SA_UNIT;
  ulonglong2* sv = (ulonglong2*)(sVbuf + u * SV_UNIT);
  ulonglong2* rowj = (ulonglong2*)(sA + j * SA_ROW);

  // Load step t0 (row j of A, x_j) — coalesced per unit.
  float4 r0 = *(const float4*)(arp), r1 = *(const float4*)(arp + 4);
  float4 m0 = *(const float4*)(aip), m1 = *(const float4*)(aip + 4);
  float vr = xrp[0], vi = xip[0];                 // v = X(t0)

  // Stage pair forms for row j.
  #define STAGE(R0, R1, I0, I1) do { \
    rowj[0] = make_ulonglong2(pk((R0).x,(R0).x), pk(-(I0).x,(I0).x)); \
    rowj[1] = make_ulonglong2(pk((R0).y,(R0).y), pk(-(I0).y,(I0).y)); \
    rowj[2] = make_ulonglong2(pk((R0).z,(R0).z), pk(-(I0).z,(I0).z)); \
    rowj[3] = make_ulonglong2(pk((R0).w,(R0).w), pk(-(I0).w,(I0).w)); \
    rowj[4] = make_ulonglong2(pk((R1).x,(R1).x), pk(-(I1).x,(I1).x)); \
    rowj[5] = make_ulonglong2(pk((R1).y,(R1).y), pk(-(I1).y,(I1).y)); \
    rowj[6] = make_ulonglong2(pk((R1).z,(R1).z), pk(-(I1).z,(I1).z)); \
    rowj[7] = make_ulonglong2(pk((R1).w,(R1).w), pk(-(I1).w,(I1).w)); \
  } while (0)

  STAGE(r0, r1, m0, m1);
  __syncwarp();

  // Init M = A(t0): column j, both packed forms cq1=(re,im), cq2=(im,re).
  ull cq1[8], cq2[8];
  #pragma unroll
  for (int i = 0; i < 8; i++) {
    ulonglong2 e = *(const ulonglong2*)(sA + i * SA_ROW + j * 16);
    float ar, ai, t_;
    upk(e.x, ar, t_);
    upk(e.y, t_, ai);
    cq1[i] = pk(ar, ai);
    cq2[i] = pk(ai, ar);
  }

  // Prefetch step t0+1.
  arp += 4096; aip += 4096; xrp += 512; xip += 512;
  float4 nr0 = *(const float4*)(arp), nr1 = *(const float4*)(arp + 4);
  float4 ni0 = *(const float4*)(aip), ni1 = *(const float4*)(aip + 4);
  float nxr = xrp[0], nxi = xip[0];

  for (int s = 1; s < T; ++s) {
    __syncwarp();                       // everyone done reading previous step
    STAGE(nr0, nr1, ni0, ni1);
    sv[j] = make_ulonglong2(pk(vr, vi), pk(vi, vr));
    const float cxr = nxr, cxi = nxi;
    if (s < T - 1) {                    // prefetch next step under the compute
      arp += 4096; aip += 4096; xrp += 512; xip += 512;
      nr0 = *(const float4*)(arp); nr1 = *(const float4*)(arp + 4);
      ni0 = *(const float4*)(aip); ni1 = *(const float4*)(aip + 4);
      nxr = xrp[0]; nxi = xip[0];
    }
    __syncwarp();                       // SMEM now holds A(t) pairs + v

    // v <- A(t) v + X(t): row j (16 packed FMAs).
    ull vS = pk(cxr, cxi);
    #pragma unroll
    for (int k = 0; k < 8; k++) {
      ulonglong2 e = rowj[k];
      ulonglong2 vk = sv[k];
      vS = ffma2(e.x, vk.x, vS);
      vS = ffma2(e.y, vk.y, vS);
    }

    // M <- A(t) @ M: column j (128 packed FMAs).
    ull ns_[8];
    #pragma unroll
    for (int i = 0; i < 8; i++) {
      const ulonglong2* rw = (const ulonglong2*)(sA + i * SA_ROW);
      ull S = 0ull;
      #pragma unroll
      for (int k = 0; k < 8; k++) {
        ulonglong2 e = rw[k];
        S = ffma2(e.x, cq1[k], S);
        S = ffma2(e.y, cq2[k], S);
      }
      ns_[i] = S;
    }
    #pragma unroll
    for (int i = 0; i < 8; i++) {
      cq1[i] = ns_[i];
      float re, im; upk(ns_[i], re, im);
      cq2[i] = pk(im, re);
    }
    upk(vS, vr, vi);
  }

  // Store column j of M (row-major for k_scan's row reads) and v[j].
  float2* gm = g_M2 + (size_t)unit * 64;
  #pragma unroll
  for (int i = 0; i < 8; i++) {
    float re, im; upk(cq1[i], re, im);
    gm[i * 8 + j] = make_float2(re, im);
  }
  g_v2[unit * 8 + j] = make_float2(vr, vi);
  #undef STAGE
}

// ---------------------------------------------------------------------------
// Kernel 2: serial scan over NCHUNK chunks per sequence. 8 threads/sequence,
// thread i owns state element i. Stores entering state E per chunk.
// ---------------------------------------------------------------------------
__global__ void k_scan()
{
  const int gid = blockIdx.x * blockDim.x + threadIdx.x;
  const int seq = gid >> 3, i = gid & 7;
  if (seq >= NSEQ) return;
  float er = 0.f, ei = 0.f;             // state entering chunk 0 is zero

  const float4* mp = (const float4*)(g_M2 + (size_t)(seq * NCHUNK) * 64 + i * 8);
  float4 m0 = mp[0], m1 = mp[1], m2 = mp[2], m3 = mp[3];
  float2 vv = g_v2[(seq * NCHUNK) * 8 + i];

  for (int ch = 0; ch < NCHUNK; ++ch) {
    const int unit = seq * NCHUNK + ch;
    g_E2[unit * 8 + i] = make_float2(er, ei);
    const float4 c0 = m0, c1 = m1, c2 = m2, c3 = m3;
    const float2 cv = vv;
    if (ch < NCHUNK - 1) {
      const float4* np = (const float4*)(g_M2 + (size_t)(unit + 1) * 64 + i * 8);
      m0 = np[0]; m1 = np[1]; m2 = np[2]; m3 = np[3];
      vv = g_v2[(unit + 1) * 8 + i];
    }
    float eor[8], eoi[8];
    #pragma unroll
    for (int k = 0; k < 8; k++) {
      eor[k] = __shfl_sync(0xffffffffu, er, k, 8);
      eoi[k] = __shfl_sync(0xffffffffu, ei, k, 8);
    }
    float sr = cv.x, si = cv.y;
    CMAC(sr, si, c0.x, c0.y, eor[0], eoi[0]);
    CMAC(sr, si, c0.z, c0.w, eor[1], eoi[1]);
    CMAC(sr, si, c1.x, c1.y, eor[2], eoi[2]);
    CMAC(sr, si, c1.z, c1.w, eor[3], eoi[3]);
    CMAC(sr, si, c2.x, c2.y, eor[4], eoi[4]);
    CMAC(sr, si, c2.z, c2.w, eor[5], eoi[5]);
    CMAC(sr, si, c3.x, c3.y, eor[6], eoi[6]);
    CMAC(sr, si, c3.z, c3.w, eor[7], eoi[7]);
    er = sr; ei = si;
  }
}

// ---------------------------------------------------------------------------
// Kernel 3: replay each chunk serially from its entering state; write Y.
// 8 threads per unit, thread j owns y[j] and reads row j of A from GMEM
// (coalesced within the unit) — memory-bound by design.
// ---------------------------------------------------------------------------
__global__ __launch_bounds__(256) void k_replay(
    const float* __restrict__ Are, const float* __restrict__ Aim,
    const float* __restrict__ Xre, const float* __restrict__ Xim,
    float2* __restrict__ out)
{
  const int tid = threadIdx.x;
  const int u = tid >> 3, j = tid & 7;
  const int unit = blockIdx.x * 32 + u;
  const int seq = unit >> 6, chunk = unit & (NCHUNK - 1);
  const int b = seq >> 6, c = seq & 63;
  const int t0 = chunk * T;

  const float* arp = Are + (size_t)(b * Lc + t0) * 4096 + c * 64 + j * 8;
  const float* aip = Aim + (size_t)(b * Lc + t0) * 4096 + c * 64 + j * 8;
  const float* xrp = Xre + (size_t)(b * Lc + t0) * 512 + c * 8 + j;
  const float* xip = Xim + (size_t)(b * Lc + t0) * 512 + c * 8 + j;
  float2* op = out + (size_t)(b * Lc + t0) * 512 + c * 8 + j;

  float2 y = g_E2[unit * 8 + j];

  float4 r0 = *(const float4*)(arp), r1 = *(const float4*)(arp + 4);
  float4 i0 = *(const float4*)(aip), i1 = *(const float4*)(aip + 4);
  float xr = xrp[0], xi = xip[0];

  for (int s = 0; s < T; ++s) {
    const float4 cr0 = r0, cr1 = r1, ci0 = i0, ci1 = i1;
    const float cxr = xr, cxi = xi;
    if (s < T - 1) {
      arp += 4096; aip += 4096; xrp += 512; xip += 512;
      r0 = *(const float4*)(arp); r1 = *(const float4*)(arp + 4);
      i0 = *(const float4*)(aip); i1 = *(const float4*)(aip + 4);
      xr = xrp[0]; xi = xip[0];
    }
    float yor[8], yoi[8];
    #pragma unroll
    for (int k = 0; k < 8; k++) {
      yor[k] = __shfl_sync(0xffffffffu, y.x, k, 8);
      yoi[k] = __shfl_sync(0xffffffffu, y.y, k, 8);
    }
    // Two parallel accumulator chains, merged at the end.
    float sr0 = cxr, si0 = cxi, sr1 = 0.f, si1 = 0.f;
    CMAC(sr0, si0, cr0.x, ci0.x, yor[0], yoi[0]);
    CMAC(sr1, si1, cr0.y, ci0.y, yor[1], yoi[1]);
    CMAC(sr0, si0, cr0.z, ci0.z, yor[2], yoi[2]);
    CMAC(sr1, si1, cr0.w, ci0.w, yor[3], yoi[3]);
    CMAC(sr0, si0, cr1.x, ci1.x, yor[4], yoi[4]);
    CMAC(sr1, si1, cr1.y, ci1.y, yor[5], yoi[5]);
    CMAC(sr0, si0, cr1.z, ci1.z, yor[6], yoi[6]);
    CMAC(sr1, si1, cr1.w, ci1.w, yor[7], yoi[7]);
    y = make_float2(sr0 + sr1, si0 + si1);
    *op = y;                            // coalesced 64 B per unit per step
    op += 512;
  }
}

// ---------------------------------------------------------------------------
extern "C" void kernel_launch(void* const* d_in, const int* in_sizes, int n_in,
                              void* d_out, int out_size)
{
  const float* Are = (const float*)d_in[0];
  const float* Aim = (const float*)d_in[1];
  const float* Xre = (const float*)d_in[2];
  const float* Xim = (const float*)d_in[3];
  float2* out = (float2*)d_out;

  k_fold<<<NUNIT / 32, 256>>>(Are, Aim, Xre, Xim);
  k_scan<<<(NSEQ * 8 + 255) / 256, 256>>>();
  k_replay<<<NUNIT / 32, 256>>>(Are, Aim, Xre, Xim, out);
}

// round 5
// speedup vs baseline: 1.0205x; 1.0205x over previous
#include <cuda_runtime.h>
#include <cuda_bf16.h>
#include <cstdint>

using ull = unsigned long long;

__device__ __forceinline__ ull pk(float lo, float hi) {
  ull r; asm("mov.b64 %0, {%1,%2};" : "=l"(r) : "f"(lo), "f"(hi)); return r;
}
__device__ __forceinline__ void upk(ull v, float& lo, float& hi) {
  asm("mov.b64 {%0,%1}, %2;" : "=f"(lo), "=f"(hi) : "l"(v));
}
__device__ __forceinline__ ull ffma2(ull a, ull b, ull c) {
  ull d; asm("fma.rn.f32x2 %0, %1, %2, %3;" : "=l"(d) : "l"(a), "l"(b), "l"(c)); return d;
}
__device__ __forceinline__ ull fadd2(ull a, ull b) {
  ull d; asm("add.rn.f32x2 %0, %1, %2;" : "=l"(d) : "l"(a), "l"(b)); return d;
}
// sr = a1.lo + a2.hi ; si = a1.hi + a2.lo
__device__ __forceinline__ ull cmerge(ull a1, ull a2) {
  float l2, h2; upk(a2, l2, h2);
  return fadd2(a1, pk(h2, l2));
}

// Scalar complex MAC: (sr,si) += (ar,ai)*(br,bi)
#define CMAC(sr, si, ar, ai, br, bi) do { \
  (sr) = fmaf((ar), (br), (sr)); (sr) = fmaf(-(ai), (bi), (sr)); \
  (si) = fmaf((ar), (bi), (si)); (si) = fmaf((ai), (br), (si)); } while (0)

constexpr int Lc = 2048;
constexpr int T = 64;                   // steps per chunk
constexpr int NCHUNK = Lc / T;          // 32
constexpr int NSEQ = 256;               // B*C
constexpr int NUNIT = NSEQ * NCHUNK;    // 8192

__device__ float2 g_M2[NUNIT * 64];     // chunk transition matrices (row-major)
__device__ float2 g_v2[NUNIT * 8];      // chunk offsets
__device__ float2 g_E2[NUNIT * 8];      // entering states

// SMEM layout: per unit, A matrix as per-element pair forms
// e1=(ar,ar), e2=(ai,-ai), 16 B/element, row stride 144 B, unit stride 1168 B
// (== 16 mod 128 -> the 4 units of a warp land on distinct banks).
constexpr int SA_ROW  = 144;
constexpr int SA_UNIT = SA_ROW * 8 + 16;   // 1168
constexpr int SV_UNIT = 80;                // 8 ull + pad

// ---------------------------------------------------------------------------
// Kernel 1: fold each chunk of T steps into (M, v): s_out = M s_in + v.
// 128 threads = 16 units; thread j owns column j of M (packed natural (re,im)).
// Per complex MAC: Acc1 += (ar,ar)*(cr,ci); Acc2 += (ai,-ai)*(cr,ci);
// merged once per dot product: S = Acc1 + swap(Acc2).
// ---------------------------------------------------------------------------
__global__ __launch_bounds__(128, 6) void k_fold(
    const float* __restrict__ Are, const float* __restrict__ Aim,
    const float* __restrict__ Xre, const float* __restrict__ Xim)
{
  __shared__ __align__(16) char sAbuf[16 * SA_UNIT];
  __shared__ __align__(16) char sVbuf[16 * SV_UNIT];

  const int tid = threadIdx.x;
  const int u = tid >> 3, j = tid & 7;
  const int unit = blockIdx.x * 16 + u;
  const int seq = unit / NCHUNK, chunk = unit % NCHUNK;
  const int b = seq >> 6, c = seq & 63;
  const int t0 = chunk * T;

  const float* arp = Are + (size_t)(b * Lc + t0) * 4096 + c * 64 + j * 8;
  const float* aip = Aim + (size_t)(b * Lc + t0) * 4096 + c * 64 + j * 8;
  const float* xrp = Xre + (size_t)(b * Lc + t0) * 512 + c * 8 + j;
  const float* xip = Xim + (size_t)(b * Lc + t0) * 512 + c * 8 + j;

  char* sA = sAbuf + u * SA_UNIT;
  ull*  sv = (ull*)(sVbuf + u * SV_UNIT);
  ulonglong2* rowj = (ulonglong2*)(sA + j * SA_ROW);

  // Stage pair forms for row j of A: e1=(ar,ar), e2=(ai,-ai).
  #define STAGE8(R0, R1, I0, I1) do { \
    rowj[0] = make_ulonglong2(pk((R0).x,(R0).x), pk((I0).x,-(I0).x)); \
    rowj[1] = make_ulonglong2(pk((R0).y,(R0).y), pk((I0).y,-(I0).y)); \
    rowj[2] = make_ulonglong2(pk((R0).z,(R0).z), pk((I0).z,-(I0).z)); \
    rowj[3] = make_ulonglong2(pk((R0).w,(R0).w), pk((I0).w,-(I0).w)); \
    rowj[4] = make_ulonglong2(pk((R1).x,(R1).x), pk((I1).x,-(I1).x)); \
    rowj[5] = make_ulonglong2(pk((R1).y,(R1).y), pk((I1).y,-(I1).y)); \
    rowj[6] = make_ulonglong2(pk((R1).z,(R1).z), pk((I1).z,-(I1).z)); \
    rowj[7] = make_ulonglong2(pk((R1).w,(R1).w), pk((I1).w,-(I1).w)); \
  } while (0)

  // Load + stage step t0.
  {
    float4 r0 = *(const float4*)(arp), r1 = *(const float4*)(arp + 4);
    float4 i0 = *(const float4*)(aip), i1 = *(const float4*)(aip + 4);
    STAGE8(r0, r1, i0, i1);
  }
  ull vpk = pk(xrp[0], xip[0]);          // v = X(t0)
  __syncwarp();

  // Init M = A(t0): column j, packed natural (re,im).
  ull cq[8];
  #pragma unroll
  for (int i = 0; i < 8; i++) {
    ulonglong2 e = *(const ulonglong2*)(sA + i * SA_ROW + j * 16);
    float ar, ai, t_;
    upk(e.x, ar, t_);
    upk(e.y, ai, t_);
    cq[i] = pk(ar, ai);
  }

  // Prefetch step t0+1.
  arp += 4096; aip += 4096; xrp += 512; xip += 512;
  float4 nr0 = *(const float4*)(arp), nr1 = *(const float4*)(arp + 4);
  float4 ni0 = *(const float4*)(aip), ni1 = *(const float4*)(aip + 4);
  float nxr = xrp[0], nxi = xip[0];

  for (int s = 1; s < T; ++s) {
    __syncwarp();                        // done reading previous step's SMEM
    STAGE8(nr0, nr1, ni0, ni1);
    sv[j] = vpk;                         // publish v(s-1)
    const float cxr = nxr, cxi = nxi;
    if (s < T - 1) {                     // prefetch next step under compute
      arp += 4096; aip += 4096; xrp += 512; xip += 512;
      nr0 = *(const float4*)(arp); nr1 = *(const float4*)(arp + 4);
      ni0 = *(const float4*)(aip); ni1 = *(const float4*)(aip + 4);
      nxr = xrp[0]; nxi = xip[0];
    }
    __syncwarp();                        // SMEM now holds A(t) forms + v

    // v <- A(t) v + X(t): row j.
    {
      ull a1 = pk(cxr, cxi), a2 = 0ull;
      #pragma unroll
      for (int k = 0; k < 8; k++) {
        ulonglong2 e = rowj[k];
        ull vk = sv[k];
        a1 = ffma2(e.x, vk, a1);
        a2 = ffma2(e.y, vk, a2);
      }
      vpk = cmerge(a1, a2);
    }

    // M <- A(t) @ M: column j.
    ull ns_[8];
    #pragma unroll
    for (int i = 0; i < 8; i++) {
      const ulonglong2* rw = (const ulonglong2*)(sA + i * SA_ROW);
      ull a1 = 0ull, a2 = 0ull;
      #pragma unroll
      for (int k = 0; k < 8; k++) {
        ulonglong2 e = rw[k];
        a1 = ffma2(e.x, cq[k], a1);
        a2 = ffma2(e.y, cq[k], a2);
      }
      ns_[i] = cmerge(a1, a2);
    }
    #pragma unroll
    for (int i = 0; i < 8; i++) cq[i] = ns_[i];
  }

  // Store column j of M (row-major for k_scan's row reads) and v[j].
  float2* gm = g_M2 + (size_t)unit * 64;
  #pragma unroll
  for (int i = 0; i < 8; i++) {
    float re, im; upk(cq[i], re, im);
    gm[i * 8 + j] = make_float2(re, im);
  }
  {
    float re, im; upk(vpk, re, im);
    g_v2[unit * 8 + j] = make_float2(re, im);
  }
  #undef STAGE8
}

// ---------------------------------------------------------------------------
// Kernel 2: serial scan over NCHUNK chunks per sequence. 8 threads/sequence,
// thread i owns state element i. Stores entering state E per chunk.
// ---------------------------------------------------------------------------
__global__ void k_scan()
{
  const int gid = blockIdx.x * blockDim.x + threadIdx.x;
  const int seq = gid >> 3, i = gid & 7;
  if (seq >= NSEQ) return;
  float er = 0.f, ei = 0.f;              // state entering chunk 0 is zero

  const float4* mp = (const float4*)(g_M2 + (size_t)(seq * NCHUNK) * 64 + i * 8);
  float4 m0 = mp[0], m1 = mp[1], m2 = mp[2], m3 = mp[3];
  float2 vv = g_v2[(seq * NCHUNK) * 8 + i];

  for (int ch = 0; ch < NCHUNK; ++ch) {
    const int unit = seq * NCHUNK + ch;
    g_E2[unit * 8 + i] = make_float2(er, ei);
    const float4 c0 = m0, c1 = m1, c2 = m2, c3 = m3;
    const float2 cv = vv;
    if (ch < NCHUNK - 1) {
      const float4* np = (const float4*)(g_M2 + (size_t)(unit + 1) * 64 + i * 8);
      m0 = np[0]; m1 = np[1]; m2 = np[2]; m3 = np[3];
      vv = g_v2[(unit + 1) * 8 + i];
    }
    float eor[8], eoi[8];
    #pragma unroll
    for (int k = 0; k < 8; k++) {
      eor[k] = __shfl_sync(0xffffffffu, er, k, 8);
      eoi[k] = __shfl_sync(0xffffffffu, ei, k, 8);
    }
    float sr = cv.x, si = cv.y;
    CMAC(sr, si, c0.x, c0.y, eor[0], eoi[0]);
    CMAC(sr, si, c0.z, c0.w, eor[1], eoi[1]);
    CMAC(sr, si, c1.x, c1.y, eor[2], eoi[2]);
    CMAC(sr, si, c1.z, c1.w, eor[3], eoi[3]);
    CMAC(sr, si, c2.x, c2.y, eor[4], eoi[4]);
    CMAC(sr, si, c2.z, c2.w, eor[5], eoi[5]);
    CMAC(sr, si, c3.x, c3.y, eor[6], eoi[6]);
    CMAC(sr, si, c3.z, c3.w, eor[7], eoi[7]);
    er = sr; ei = si;
  }
}

// ---------------------------------------------------------------------------
// Kernel 3: replay each chunk serially from its entering state; write Y.
// 8 threads per unit, thread j owns y[j] and reads row j of A from GMEM
// (coalesced within the unit) — memory-bound by design.
// ---------------------------------------------------------------------------
__global__ __launch_bounds__(256) void k_replay(
    const float* __restrict__ Are, const float* __restrict__ Aim,
    const float* __restrict__ Xre, const float* __restrict__ Xim,
    float2* __restrict__ out)
{
  const int tid = threadIdx.x;
  const int u = tid >> 3, j = tid & 7;
  const int unit = blockIdx.x * 32 + u;
  const int seq = unit / NCHUNK, chunk = unit % NCHUNK;
  const int b = seq >> 6, c = seq & 63;
  const int t0 = chunk * T;

  const float* arp = Are + (size_t)(b * Lc + t0) * 4096 + c * 64 + j * 8;
  const float* aip = Aim + (size_t)(b * Lc + t0) * 4096 + c * 64 + j * 8;
  const float* xrp = Xre + (size_t)(b * Lc + t0) * 512 + c * 8 + j;
  const float* xip = Xim + (size_t)(b * Lc + t0) * 512 + c * 8 + j;
  float2* op = out + (size_t)(b * Lc + t0) * 512 + c * 8 + j;

  float2 y = g_E2[unit * 8 + j];

  float4 r0 = *(const float4*)(arp), r1 = *(const float4*)(arp + 4);
  float4 i0 = *(const float4*)(aip), i1 = *(const float4*)(aip + 4);
  float xr = xrp[0], xi = xip[0];

  for (int s = 0; s < T; ++s) {
    const float4 cr0 = r0, cr1 = r1, ci0 = i0, ci1 = i1;
    const float cxr = xr, cxi = xi;
    if (s < T - 1) {
      arp += 4096; aip += 4096; xrp += 512; xip += 512;
      r0 = *(const float4*)(arp); r1 = *(const float4*)(arp + 4);
      i0 = *(const float4*)(aip); i1 = *(const float4*)(aip + 4);
      xr = xrp[0]; xi = xip[0];
    }
    float yor[8], yoi[8];
    #pragma unroll
    for (int k = 0; k < 8; k++) {
      yor[k] = __shfl_sync(0xffffffffu, y.x, k, 8);
      yoi[k] = __shfl_sync(0xffffffffu, y.y, k, 8);
    }
    // Two parallel accumulator chains, merged at the end.
    float sr0 = cxr, si0 = cxi, sr1 = 0.f, si1 = 0.f;
    CMAC(sr0, si0, cr0.x, ci0.x, yor[0], yoi[0]);
    CMAC(sr1, si1, cr0.y, ci0.y, yor[1], yoi[1]);
    CMAC(sr0, si0, cr0.z, ci0.z, yor[2], yoi[2]);
    CMAC(sr1, si1, cr0.w, ci0.w, yor[3], yoi[3]);
    CMAC(sr0, si0, cr1.x, ci1.x, yor[4], yoi[4]);
    CMAC(sr1, si1, cr1.y, ci1.y, yor[5], yoi[5]);
    CMAC(sr0, si0, cr1.z, ci1.z, yor[6], yoi[6]);
    CMAC(sr1, si1, cr1.w, ci1.w, yor[7], yoi[7]);
    y = make_float2(sr0 + sr1, si0 + si1);
    *op = y;                             // coalesced 64 B per unit per step
    op += 512;
  }
}

// ---------------------------------------------------------------------------
extern "C" void kernel_launch(void* const* d_in, const int* in_sizes, int n_in,
                              void* d_out, int out_size)
{
  const float* Are = (const float*)d_in[0];
  const float* Aim = (const float*)d_in[1];
  const float* Xre = (const float*)d_in[2];
  const float* Xim = (const float*)d_in[3];
  float2* out = (float2*)d_out;

  k_fold<<<NUNIT / 16, 128>>>(Are, Aim, Xre, Xim);
  k_scan<<<(NSEQ * 8 + 255) / 256, 256>>>();
  k_replay<<<NUNIT / 32, 256>>>(Are, Aim, Xre, Xim, out);
}

// round 7
// speedup vs baseline: 1.0814x; 1.0597x over previous
#include <cuda_runtime.h>
#include <cuda_bf16.h>
#include <cstdint>

using ull = unsigned long long;

__device__ __forceinline__ ull pk(float lo, float hi) {
  ull r; asm("mov.b64 %0, {%1,%2};" : "=l"(r) : "f"(lo), "f"(hi)); return r;
}
__device__ __forceinline__ void upk(ull v, float& lo, float& hi) {
  asm("mov.b64 {%0,%1}, %2;" : "=f"(lo), "=f"(hi) : "l"(v));
}
__device__ __forceinline__ ull ffma2(ull a, ull b, ull c) {
  ull d; asm("fma.rn.f32x2 %0, %1, %2, %3;" : "=l"(d) : "l"(a), "l"(b), "l"(c)); return d;
}
__device__ __forceinline__ void cpa16(uint32_t dst, const void* src) {
  asm volatile("cp.async.ca.shared.global [%0], [%1], 16;" :: "r"(dst), "l"(src));
}
#define CP_COMMIT() asm volatile("cp.async.commit_group;")
#define CP_WAIT1()  asm volatile("cp.async.wait_group 1;")

// Scalar complex MAC: (sr,si) += (ar,ai)*(br,bi)
#define CMAC(sr, si, ar, ai, br, bi) do { \
  (sr) = fmaf((ar), (br), (sr)); (sr) = fmaf(-(ai), (bi), (sr)); \
  (si) = fmaf((ar), (bi), (si)); (si) = fmaf((ai), (br), (si)); } while (0)

constexpr int Lc = 2048;
constexpr int T = 16;                   // steps per chunk
constexpr int NCHUNK = Lc / T;          // 128
constexpr int NSEQ = 256;               // B*C
constexpr int NUNIT = NSEQ * NCHUNK;    // 32768

__device__ float2 g_M2[NUNIT * 64];     // 16 MB: chunk transition matrices
__device__ float2 g_v2[NUNIT * 8];      // 2 MB: chunk offsets
__device__ float2 g_E2[NUNIT * 8];      // 2 MB: entering states

// Fold SMEM per unit (stride 1232 B; 1232 mod 128 = 80 -> the 8 units of a
// warp hit distinct 16B banks for every broadcast access):
//   [0,512)    A stage0: re 256 B, im 256 B   (raw floats, row i at +i*32)
//   [512,1024) A stage1
//   [1024,1088) x stage0: re 32 B, im 32 B
//   [1088,1152) x stage1
//   [1152,1216) v: 8 packed (re,im) ull
constexpr int FU_STRIDE = 1232;

// ---------------------------------------------------------------------------
// Kernel 1: fold T steps into (M, v). 64 threads = 16 units; 4 lanes/unit;
// lane h owns M columns h and h+4, and v rows h and h+4.
// Complex MAC via dup-A / raw-M:
//   acc1 += (ar,ar)*(mr,mi); acc2 += (ai,ai)*(mr,mi);
//   Re = acc1.lo - acc2.hi;  Im = acc1.hi + acc2.lo.
// ---------------------------------------------------------------------------
__global__ __launch_bounds__(64, 8) void k_fold(
    const float* __restrict__ Are, const float* __restrict__ Aim,
    const float* __restrict__ Xre, const float* __restrict__ Xim)
{
  __shared__ __align__(16) char smraw[16 * FU_STRIDE];

  const int tid = threadIdx.x;
  const int u = tid >> 2, h = tid & 3;
  const int bid = blockIdx.x;                 // = ((b*128 + chunk)*4 + cg)
  const int cg = bid & 3;
  const int chunk = (bid >> 2) & 127;
  const int b = bid >> 9;
  const int c = cg * 16 + u;
  const int unit = (b * 64 + c) * NCHUNK + chunk;
  const int t0 = chunk * T;

  const float* aRe = Are + ((size_t)(b * Lc + t0) * 64 + c) * 64;
  const float* aIm = Aim + ((size_t)(b * Lc + t0) * 64 + c) * 64;
  const float* xRe = Xre + ((size_t)(b * Lc + t0) * 64 + c) * 8;
  const float* xIm = Xim + ((size_t)(b * Lc + t0) * 64 + c) * 8;

  char* su = smraw + u * FU_STRIDE;
  const uint32_t suA = (uint32_t)__cvta_generic_to_shared(su);
  ull* vbuf = (ull*)(su + 1152);

  // Stage step t into buffer st: lane h copies A rows 2h,2h+1 (re 64B + im
  // 64B); lanes 2/3 copy x re/im. All 16B cp.async, perfectly coalesced.
  #define STAGE(t, st) do { \
    const float* r_ = aRe + (t) * 4096 + h * 16; \
    const float* i_ = aIm + (t) * 4096 + h * 16; \
    uint32_t d_ = suA + (st) * 512 + h * 64; \
    cpa16(d_, r_); cpa16(d_ + 16, r_ + 4); cpa16(d_ + 32, r_ + 8); cpa16(d_ + 48, r_ + 12); \
    cpa16(d_ + 256, i_); cpa16(d_ + 272, i_ + 4); cpa16(d_ + 288, i_ + 8); cpa16(d_ + 304, i_ + 12); \
    if (h == 2) { const float* x_ = xRe + (t) * 512; uint32_t dx_ = suA + 1024 + (st) * 64; \
      cpa16(dx_, x_); cpa16(dx_ + 16, x_ + 4); } \
    if (h == 3) { const float* x_ = xIm + (t) * 512; uint32_t dx_ = suA + 1024 + (st) * 64 + 32; \
      cpa16(dx_, x_); cpa16(dx_ + 16, x_ + 4); } \
  } while (0)

  STAGE(0, 0); CP_COMMIT();
  STAGE(1, 1); CP_COMMIT();
  CP_WAIT1();
  __syncwarp();

  const int c0 = h, c1 = h + 4;

  // Init M = A(t0) (cols c0,c1), v = X(t0).
  ull Mc0[8], Mc1[8];
  {
    const float* sre = (const float*)(su);
    const float* sim = (const float*)(su + 256);
    #pragma unroll
    for (int i = 0; i < 8; i++) {
      Mc0[i] = pk(sre[i * 8 + c0], sim[i * 8 + c0]);
      Mc1[i] = pk(sre[i * 8 + c1], sim[i * 8 + c1]);
    }
    const float* xr = (const float*)(su + 1024);
    const float* xi = xr + 8;
    vbuf[c0] = pk(xr[c0], xi[c0]);
    vbuf[c1] = pk(xr[c1], xi[c1]);
  }
  __syncwarp();                  // stage0 reads done; v visible

  ull vnew0 = vbuf[c0], vnew1 = vbuf[c1];

  for (int s = 1; s < T; ++s) {
    if (s + 1 < T) STAGE(s + 1, (s + 1) & 1);
    CP_COMMIT();                 // commit (possibly empty) group
    CP_WAIT1();                  // A(t_s)/x(t_s) now resident
    __syncwarp();                // visible to all lanes; v(s-1) visible too

    const char* stg = su + (s & 1) * 512;
    const float* sre = (const float*)(stg);
    const float* sim = (const float*)(stg + 256);

    // M <- A(t_s) @ M (cols c0, c1).
    ull n0[8], n1[8];
    #pragma unroll
    for (int i = 0; i < 8; i++) {
      const float4* rr = (const float4*)(sre + i * 8);
      const float4* ii = (const float4*)(sim + i * 8);
      float4 ra = rr[0], rb = rr[1], ia = ii[0], ib = ii[1];
      ull a10 = 0, a20 = 0, a11 = 0, a21 = 0;
      #define STEPK(RF, IF, K) do { \
        ull dr_ = pk((RF), (RF)); ull di_ = pk((IF), (IF)); \
        a10 = ffma2(dr_, Mc0[K], a10); a20 = ffma2(di_, Mc0[K], a20); \
        a11 = ffma2(dr_, Mc1[K], a11); a21 = ffma2(di_, Mc1[K], a21); } while (0)
      STEPK(ra.x, ia.x, 0); STEPK(ra.y, ia.y, 1);
      STEPK(ra.z, ia.z, 2); STEPK(ra.w, ia.w, 3);
      STEPK(rb.x, ib.x, 4); STEPK(rb.y, ib.y, 5);
      STEPK(rb.z, ib.z, 6); STEPK(rb.w, ib.w, 7);
      #undef STEPK
      float l1, h1, l2, h2;
      upk(a10, l1, h1); upk(a20, l2, h2);
      n0[i] = pk(l1 - h2, h1 + l2);
      upk(a11, l1, h1); upk(a21, l2, h2);
      n1[i] = pk(l1 - h2, h1 + l2);
    }

    // v <- A(t_s) v + x(t_s): rows c0, c1 (v read raw from SMEM).
    {
      const ulonglong2* vb2 = (const ulonglong2*)vbuf;
      ulonglong2 q0 = vb2[0], q1 = vb2[1], q2 = vb2[2], q3 = vb2[3];
      ull vv[8] = {q0.x, q0.y, q1.x, q1.y, q2.x, q2.y, q3.x, q3.y};
      const float* xr = (const float*)(su + 1024 + (s & 1) * 64);
      const float* xi = xr + 8;
      #pragma unroll
      for (int rsel = 0; rsel < 2; rsel++) {
        const int r = rsel ? c1 : c0;
        const float4* rr = (const float4*)(sre + r * 8);
        const float4* ii = (const float4*)(sim + r * 8);
        float4 ra = rr[0], rb = rr[1], ia = ii[0], ib = ii[1];
        ull a1 = pk(xr[r], xi[r]), a2 = 0;
        #define VK(RF, IF, K) do { \
          ull dr_ = pk((RF), (RF)); ull di_ = pk((IF), (IF)); \
          a1 = ffma2(dr_, vv[K], a1); a2 = ffma2(di_, vv[K], a2); } while (0)
        VK(ra.x, ia.x, 0); VK(ra.y, ia.y, 1); VK(ra.z, ia.z, 2); VK(ra.w, ia.w, 3);
        VK(rb.x, ib.x, 4); VK(rb.y, ib.y, 5); VK(rb.z, ib.z, 6); VK(rb.w, ib.w, 7);
        #undef VK
        float l1, h1, l2, h2; upk(a1, l1, h1); upk(a2, l2, h2);
        ull res = pk(l1 - h2, h1 + l2);
        if (rsel) vnew1 = res; else vnew0 = res;
      }
    }

    #pragma unroll
    for (int i = 0; i < 8; i++) { Mc0[i] = n0[i]; Mc1[i] = n1[i]; }
    __syncwarp();                // all lanes done reading v-old and this stage
    vbuf[c0] = vnew0; vbuf[c1] = vnew1;
  }

  // Store M (row-major, for k_scan's coalesced row reads) and v.
  float2* gm = g_M2 + (size_t)unit * 64;
  #pragma unroll
  for (int i = 0; i < 8; i++) {
    float re, im;
    upk(Mc0[i], re, im); gm[i * 8 + c0] = make_float2(re, im);
    upk(Mc1[i], re, im); gm[i * 8 + c1] = make_float2(re, im);
  }
  {
    float re, im;
    upk(vnew0, re, im); g_v2[unit * 8 + c0] = make_float2(re, im);
    upk(vnew1, re, im); g_v2[unit * 8 + c1] = make_float2(re, im);
  }
  #undef STAGE
}

// ---------------------------------------------------------------------------
// Kernel 2: serial scan over NCHUNK chunks per sequence. 8 threads/sequence,
// thread i owns state element i. Stores entering state E per chunk.
// ---------------------------------------------------------------------------
__global__ void k_scan()
{
  const int gid = blockIdx.x * blockDim.x + threadIdx.x;
  const int seq = gid >> 3, i = gid & 7;
  if (seq >= NSEQ) return;
  float er = 0.f, ei = 0.f;            // state entering chunk 0 is zero

  const float4* mp = (const float4*)(g_M2 + (size_t)(seq * NCHUNK) * 64 + i * 8);
  float4 m0 = mp[0], m1 = mp[1], m2 = mp[2], m3 = mp[3];
  float2 vv = g_v2[(seq * NCHUNK) * 8 + i];

  for (int ch = 0; ch < NCHUNK; ++ch) {
    const int unit = seq * NCHUNK + ch;
    g_E2[unit * 8 + i] = make_float2(er, ei);
    const float4 c0 = m0, c1 = m1, c2 = m2, c3 = m3;
    const float2 cv = vv;
    if (ch < NCHUNK - 1) {
      const float4* np = (const float4*)(g_M2 + (size_t)(unit + 1) * 64 + i * 8);
      m0 = np[0]; m1 = np[1]; m2 = np[2]; m3 = np[3];
      vv = g_v2[(unit + 1) * 8 + i];
    }
    float eor[8], eoi[8];
    #pragma unroll
    for (int k = 0; k < 8; k++) {
      eor[k] = __shfl_sync(0xffffffffu, er, k, 8);
      eoi[k] = __shfl_sync(0xffffffffu, ei, k, 8);
    }
    float sr = cv.x, si = cv.y;
    CMAC(sr, si, c0.x, c0.y, eor[0], eoi[0]);
    CMAC(sr, si, c0.z, c0.w, eor[1], eoi[1]);
    CMAC(sr, si, c1.x, c1.y, eor[2], eoi[2]);
    CMAC(sr, si, c1.z, c1.w, eor[3], eoi[3]);
    CMAC(sr, si, c2.x, c2.y, eor[4], eoi[4]);
    CMAC(sr, si, c2.z, c2.w, eor[5], eoi[5]);
    CMAC(sr, si, c3.x, c3.y, eor[6], eoi[6]);
    CMAC(sr, si, c3.z, c3.w, eor[7], eoi[7]);
    er = sr; ei = si;
  }
}

// ---------------------------------------------------------------------------
// Kernel 3: replay each chunk from its entering state; write Y.
// 256 threads = 32 units (c-major for coalescing); 8 lanes/unit.
// ---------------------------------------------------------------------------
__global__ __launch_bounds__(256) void k_replay(
    const float* __restrict__ Are, const float* __restrict__ Aim,
    const float* __restrict__ Xre, const float* __restrict__ Xim,
    float2* __restrict__ out)
{
  const int tid = threadIdx.x;
  const int u = tid >> 3, j = tid & 7;
  const int bid = blockIdx.x;                // = ((b*128 + chunk)*2 + cg)
  const int cg = bid & 1;
  const int chunk = (bid >> 1) & 127;
  const int b = bid >> 8;
  const int c = cg * 32 + u;
  const int unit = (b * 64 + c) * NCHUNK + chunk;
  const int t0 = chunk * T;

  const float* arp = Are + ((size_t)(b * Lc + t0) * 64 + c) * 64 + j * 8;
  const float* aip = Aim + ((size_t)(b * Lc + t0) * 64 + c) * 64 + j * 8;
  const float* xrp = Xre + ((size_t)(b * Lc + t0) * 64 + c) * 8 + j;
  const float* xip = Xim + ((size_t)(b * Lc + t0) * 64 + c) * 8 + j;
  float2* op = out + ((size_t)(b * Lc + t0) * 64 + c) * 8 + j;

  float2 y = g_E2[unit * 8 + j];

  float4 r0 = *(const float4*)(arp), r1 = *(const float4*)(arp + 4);
  float4 i0 = *(const float4*)(aip), i1 = *(const float4*)(aip + 4);
  float xr = xrp[0], xi = xip[0];

  for (int s = 0; s < T; ++s) {
    const float4 cr0 = r0, cr1 = r1, ci0 = i0, ci1 = i1;
    const float cxr = xr, cxi = xi;
    if (s < T - 1) {
      arp += 4096; aip += 4096; xrp += 512; xip += 512;
      r0 = *(const float4*)(arp); r1 = *(const float4*)(arp + 4);
      i0 = *(const float4*)(aip); i1 = *(const float4*)(aip + 4);
      xr = xrp[0]; xi = xip[0];
    }
    float yor[8], yoi[8];
    #pragma unroll
    for (int k = 0; k < 8; k++) {
      yor[k] = __shfl_sync(0xffffffffu, y.x, k, 8);
      yoi[k] = __shfl_sync(0xffffffffu, y.y, k, 8);
    }
    float sr0 = cxr, si0 = cxi, sr1 = 0.f, si1 = 0.f;
    CMAC(sr0, si0, cr0.x, ci0.x, yor[0], yoi[0]);
    CMAC(sr1, si1, cr0.y, ci0.y, yor[1], yoi[1]);
    CMAC(sr0, si0, cr0.z, ci0.z, yor[2], yoi[2]);
    CMAC(sr1, si1, cr0.w, ci0.w, yor[3], yoi[3]);
    CMAC(sr0, si0, cr1.x, ci1.x, yor[4], yoi[4]);
    CMAC(sr1, si1, cr1.y, ci1.y, yor[5], yoi[5]);
    CMAC(sr0, si0, cr1.z, ci1.z, yor[6], yoi[6]);
    CMAC(sr1, si1, cr1.w, ci1.w, yor[7], yoi[7]);
    y = make_float2(sr0 + sr1, si0 + si1);
    *op = y;
    op += 512;
  }
}

// ---------------------------------------------------------------------------
extern "C" void kernel_launch(void* const* d_in, const int* in_sizes, int n_in,
                              void* d_out, int out_size)
{
  const float* Are = (const float*)d_in[0];
  const float* Aim = (const float*)d_in[1];
  const float* Xre = (const float*)d_in[2];
  const float* Xim = (const float*)d_in[3];
  float2* out = (float2*)d_out;

  k_fold<<<4 * 128 * 4, 64>>>(Are, Aim, Xre, Xim);       // 2048 CTAs
  k_scan<<<(NSEQ * 8 + 255) / 256, 256>>>();             // 8 CTAs
  k_replay<<<4 * 128 * 2, 256>>>(Are, Aim, Xre, Xim, out); // 1024 CTAs
}

// round 9
// speedup vs baseline: 1.2817x; 1.1853x over previous
#include <cuda_runtime.h>
#include <cuda_bf16.h>
#include <cstdint>

using ull = unsigned long long;

__device__ __forceinline__ ull pk(float lo, float hi) {
  ull r; asm("mov.b64 %0, {%1,%2};" : "=l"(r) : "f"(lo), "f"(hi)); return r;
}
__device__ __forceinline__ void upk(ull v, float& lo, float& hi) {
  asm("mov.b64 {%0,%1}, %2;" : "=f"(lo), "=f"(hi) : "l"(v));
}
__device__ __forceinline__ ull ffma2(ull a, ull b, ull c) {
  ull d; asm("fma.rn.f32x2 %0, %1, %2, %3;" : "=l"(d) : "l"(a), "l"(b), "l"(c)); return d;
}
__device__ __forceinline__ void cpa16(uint32_t dst, const void* src) {
  asm volatile("cp.async.ca.shared.global [%0], [%1], 16;" :: "r"(dst), "l"(src));
}
#define CP_COMMIT() asm volatile("cp.async.commit_group;")
#define CP_WAIT1()  asm volatile("cp.async.wait_group 1;")

// Scalar complex MAC: (sr,si) += (ar,ai)*(br,bi)
#define CMAC(sr, si, ar, ai, br, bi) do { \
  (sr) = fmaf((ar), (br), (sr)); (sr) = fmaf(-(ai), (bi), (sr)); \
  (si) = fmaf((ar), (bi), (si)); (si) = fmaf((ai), (br), (si)); } while (0)

constexpr int Lc = 2048;
constexpr int T = 16;                   // steps per chunk
constexpr int NCHUNK = Lc / T;          // 128
constexpr int NSEQ = 256;               // B*C
constexpr int NUNIT = NSEQ * NCHUNK;    // 32768

__device__ float2 g_M2[NUNIT * 64];     // 16 MB: chunk transition matrices
__device__ float2 g_v2[NUNIT * 8];      // 2 MB: chunk offsets
__device__ float2 g_E2[NUNIT * 8];      // 2 MB: entering states

constexpr int FU_STRIDE = 1232;

// ---------------------------------------------------------------------------
// Kernel 1: fold T steps into (M, v). Unchanged from R7 (verified 71.5us).
// ---------------------------------------------------------------------------
__global__ __launch_bounds__(64, 8) void k_fold(
    const float* __restrict__ Are, const float* __restrict__ Aim,
    const float* __restrict__ Xre, const float* __restrict__ Xim)
{
  __shared__ __align__(16) char smraw[16 * FU_STRIDE];

  const int tid = threadIdx.x;
  const int u = tid >> 2, h = tid & 3;
  const int bid = blockIdx.x;                 // = ((b*128 + chunk)*4 + cg)
  const int cg = bid & 3;
  const int chunk = (bid >> 2) & 127;
  const int b = bid >> 9;
  const int c = cg * 16 + u;
  const int unit = (b * 64 + c) * NCHUNK + chunk;
  const int t0 = chunk * T;

  const float* aRe = Are + ((size_t)(b * Lc + t0) * 64 + c) * 64;
  const float* aIm = Aim + ((size_t)(b * Lc + t0) * 64 + c) * 64;
  const float* xRe = Xre + ((size_t)(b * Lc + t0) * 64 + c) * 8;
  const float* xIm = Xim + ((size_t)(b * Lc + t0) * 64 + c) * 8;

  char* su = smraw + u * FU_STRIDE;
  const uint32_t suA = (uint32_t)__cvta_generic_to_shared(su);
  ull* vbuf = (ull*)(su + 1152);

  #define STAGE(t, st) do { \
    const float* r_ = aRe + (t) * 4096 + h * 16; \
    const float* i_ = aIm + (t) * 4096 + h * 16; \
    uint32_t d_ = suA + (st) * 512 + h * 64; \
    cpa16(d_, r_); cpa16(d_ + 16, r_ + 4); cpa16(d_ + 32, r_ + 8); cpa16(d_ + 48, r_ + 12); \
    cpa16(d_ + 256, i_); cpa16(d_ + 272, i_ + 4); cpa16(d_ + 288, i_ + 8); cpa16(d_ + 304, i_ + 12); \
    if (h == 2) { const float* x_ = xRe + (t) * 512; uint32_t dx_ = suA + 1024 + (st) * 64; \
      cpa16(dx_, x_); cpa16(dx_ + 16, x_ + 4); } \
    if (h == 3) { const float* x_ = xIm + (t) * 512; uint32_t dx_ = suA + 1024 + (st) * 64 + 32; \
      cpa16(dx_, x_); cpa16(dx_ + 16, x_ + 4); } \
  } while (0)

  STAGE(0, 0); CP_COMMIT();
  STAGE(1, 1); CP_COMMIT();
  CP_WAIT1();
  __syncwarp();

  const int c0 = h, c1 = h + 4;

  ull Mc0[8], Mc1[8];
  {
    const float* sre = (const float*)(su);
    const float* sim = (const float*)(su + 256);
    #pragma unroll
    for (int i = 0; i < 8; i++) {
      Mc0[i] = pk(sre[i * 8 + c0], sim[i * 8 + c0]);
      Mc1[i] = pk(sre[i * 8 + c1], sim[i * 8 + c1]);
    }
    const float* xr = (const float*)(su + 1024);
    const float* xi = xr + 8;
    vbuf[c0] = pk(xr[c0], xi[c0]);
    vbuf[c1] = pk(xr[c1], xi[c1]);
  }
  __syncwarp();

  ull vnew0 = vbuf[c0], vnew1 = vbuf[c1];

  for (int s = 1; s < T; ++s) {
    if (s + 1 < T) STAGE(s + 1, (s + 1) & 1);
    CP_COMMIT();
    CP_WAIT1();
    __syncwarp();

    const char* stg = su + (s & 1) * 512;
    const float* sre = (const float*)(stg);
    const float* sim = (const float*)(stg + 256);

    ull n0[8], n1[8];
    #pragma unroll
    for (int i = 0; i < 8; i++) {
      const float4* rr = (const float4*)(sre + i * 8);
      const float4* ii = (const float4*)(sim + i * 8);
      float4 ra = rr[0], rb = rr[1], ia = ii[0], ib = ii[1];
      ull a10 = 0, a20 = 0, a11 = 0, a21 = 0;
      #define STEPK(RF, IF, K) do { \
        ull dr_ = pk((RF), (RF)); ull di_ = pk((IF), (IF)); \
        a10 = ffma2(dr_, Mc0[K], a10); a20 = ffma2(di_, Mc0[K], a20); \
        a11 = ffma2(dr_, Mc1[K], a11); a21 = ffma2(di_, Mc1[K], a21); } while (0)
      STEPK(ra.x, ia.x, 0); STEPK(ra.y, ia.y, 1);
      STEPK(ra.z, ia.z, 2); STEPK(ra.w, ia.w, 3);
      STEPK(rb.x, ib.x, 4); STEPK(rb.y, ib.y, 5);
      STEPK(rb.z, ib.z, 6); STEPK(rb.w, ib.w, 7);
      #undef STEPK
      float l1, h1, l2, h2;
      upk(a10, l1, h1); upk(a20, l2, h2);
      n0[i] = pk(l1 - h2, h1 + l2);
      upk(a11, l1, h1); upk(a21, l2, h2);
      n1[i] = pk(l1 - h2, h1 + l2);
    }

    {
      const ulonglong2* vb2 = (const ulonglong2*)vbuf;
      ulonglong2 q0 = vb2[0], q1 = vb2[1], q2 = vb2[2], q3 = vb2[3];
      ull vv[8] = {q0.x, q0.y, q1.x, q1.y, q2.x, q2.y, q3.x, q3.y};
      const float* xr = (const float*)(su + 1024 + (s & 1) * 64);
      const float* xi = xr + 8;
      #pragma unroll
      for (int rsel = 0; rsel < 2; rsel++) {
        const int r = rsel ? c1 : c0;
        const float4* rr = (const float4*)(sre + r * 8);
        const float4* ii = (const float4*)(sim + r * 8);
        float4 ra = rr[0], rb = rr[1], ia = ii[0], ib = ii[1];
        ull a1 = pk(xr[r], xi[r]), a2 = 0;
        #define VK(RF, IF, K) do { \
          ull dr_ = pk((RF), (RF)); ull di_ = pk((IF), (IF)); \
          a1 = ffma2(dr_, vv[K], a1); a2 = ffma2(di_, vv[K], a2); } while (0)
        VK(ra.x, ia.x, 0); VK(ra.y, ia.y, 1); VK(ra.z, ia.z, 2); VK(ra.w, ia.w, 3);
        VK(rb.x, ib.x, 4); VK(rb.y, ib.y, 5); VK(rb.z, ib.z, 6); VK(rb.w, ib.w, 7);
        #undef VK
        float l1, h1, l2, h2; upk(a1, l1, h1); upk(a2, l2, h2);
        ull res = pk(l1 - h2, h1 + l2);
        if (rsel) vnew1 = res; else vnew0 = res;
      }
    }

    #pragma unroll
    for (int i = 0; i < 8; i++) { Mc0[i] = n0[i]; Mc1[i] = n1[i]; }
    __syncwarp();
    vbuf[c0] = vnew0; vbuf[c1] = vnew1;
  }

  float2* gm = g_M2 + (size_t)unit * 64;
  #pragma unroll
  for (int i = 0; i < 8; i++) {
    float re, im;
    upk(Mc0[i], re, im); gm[i * 8 + c0] = make_float2(re, im);
    upk(Mc1[i], re, im); gm[i * 8 + c1] = make_float2(re, im);
  }
  {
    float re, im;
    upk(vnew0, re, im); g_v2[unit * 8 + c0] = make_float2(re, im);
    upk(vnew1, re, im); g_v2[unit * 8 + c1] = make_float2(re, im);
  }
  #undef STAGE
}

// ---------------------------------------------------------------------------
// Kernel 2: serial scan over NCHUNK chunk summaries per sequence, with a
// 4-deep register prefetch ring so the 128-long dependent chain is bounded
// by the ~120-cycle compute per hop, not by memory latency.
// ---------------------------------------------------------------------------
__global__ void k_scan()
{
  const int gid = blockIdx.x * blockDim.x + threadIdx.x;
  const int seq = gid >> 3, i = gid & 7;
  if (seq >= NSEQ) return;
  float er = 0.f, ei = 0.f;             // state entering chunk 0 is zero

  const float2* mbase = g_M2 + (size_t)(seq * NCHUNK) * 64;
  const float2* vbase = g_v2 + (size_t)(seq * NCHUNK) * 8;
  float2* ebase = g_E2 + (size_t)(seq * NCHUNK) * 8;

  float4 m[4][4];
  float2 vv[4];
  #pragma unroll
  for (int p = 0; p < 4; p++) {
    const float4* mp = (const float4*)(mbase + p * 64 + i * 8);
    m[p][0] = mp[0]; m[p][1] = mp[1]; m[p][2] = mp[2]; m[p][3] = mp[3];
    vv[p] = vbase[p * 8 + i];
  }

  #pragma unroll 4
  for (int ch = 0; ch < NCHUNK; ++ch) {
    const int slot = ch & 3;
    ebase[ch * 8 + i] = make_float2(er, ei);
    const float4 c0 = m[slot][0], c1 = m[slot][1];
    const float4 c2 = m[slot][2], c3 = m[slot][3];
    const float2 cv = vv[slot];
    if (ch + 4 < NCHUNK) {
      const float4* np = (const float4*)(mbase + (ch + 4) * 64 + i * 8);
      m[slot][0] = np[0]; m[slot][1] = np[1];
      m[slot][2] = np[2]; m[slot][3] = np[3];
      vv[slot] = vbase[(ch + 4) * 8 + i];
    }
    float eor[8], eoi[8];
    #pragma unroll
    for (int k = 0; k < 8; k++) {
      eor[k] = __shfl_sync(0xffffffffu, er, k, 8);
      eoi[k] = __shfl_sync(0xffffffffu, ei, k, 8);
    }
    // Two parallel accumulator chains.
    float sr0 = cv.x, si0 = cv.y, sr1 = 0.f, si1 = 0.f;
    CMAC(sr0, si0, c0.x, c0.y, eor[0], eoi[0]);
    CMAC(sr1, si1, c0.z, c0.w, eor[1], eoi[1]);
    CMAC(sr0, si0, c1.x, c1.y, eor[2], eoi[2]);
    CMAC(sr1, si1, c1.z, c1.w, eor[3], eoi[3]);
    CMAC(sr0, si0, c2.x, c2.y, eor[4], eoi[4]);
    CMAC(sr1, si1, c2.z, c2.w, eor[5], eoi[5]);
    CMAC(sr0, si0, c3.x, c3.y, eor[6], eoi[6]);
    CMAC(sr1, si1, c3.z, c3.w, eor[7], eoi[7]);
    er = sr0 + sr1; ei = si0 + si1;
  }
}

// ---------------------------------------------------------------------------
// Kernel 3: replay each chunk from its entering state; write Y.
// 128 threads = 16 units (c-major mapping identical to k_fold); 8 lanes/unit.
// ---------------------------------------------------------------------------
__global__ __launch_bounds__(128) void k_replay(
    const float* __restrict__ Are, const float* __restrict__ Aim,
    const float* __restrict__ Xre, const float* __restrict__ Xim,
    float2* __restrict__ out)
{
  const int tid = threadIdx.x;
  const int u = tid >> 3, j = tid & 7;
  const int bid = blockIdx.x;                // = ((b*128 + chunk)*4 + cg)
  const int cg = bid & 3;
  const int chunk = (bid >> 2) & 127;
  const int b = bid >> 9;
  const int c = cg * 16 + u;
  const int unit = (b * 64 + c) * NCHUNK + chunk;
  const int t0 = chunk * T;

  const float* arp = Are + ((size_t)(b * Lc + t0) * 64 + c) * 64 + j * 8;
  const float* aip = Aim + ((size_t)(b * Lc + t0) * 64 + c) * 64 + j * 8;
  const float* xrp = Xre + ((size_t)(b * Lc + t0) * 64 + c) * 8 + j;
  const float* xip = Xim + ((size_t)(b * Lc + t0) * 64 + c) * 8 + j;
  float2* op = out + ((size_t)(b * Lc + t0) * 64 + c) * 8 + j;

  float2 y = g_E2[unit * 8 + j];

  float4 r0 = *(const float4*)(arp), r1 = *(const float4*)(arp + 4);
  float4 i0 = *(const float4*)(aip), i1 = *(const float4*)(aip + 4);
  float xr = xrp[0], xi = xip[0];

  for (int s = 0; s < T; ++s) {
    const float4 cr0 = r0, cr1 = r1, ci0 = i0, ci1 = i1;
    const float cxr = xr, cxi = xi;
    if (s < T - 1) {
      arp += 4096; aip += 4096; xrp += 512; xip += 512;
      r0 = *(const float4*)(arp); r1 = *(const float4*)(arp + 4);
      i0 = *(const float4*)(aip); i1 = *(const float4*)(aip + 4);
      xr = xrp[0]; xi = xip[0];
    }
    float yor[8], yoi[8];
    #pragma unroll
    for (int k = 0; k < 8; k++) {
      yor[k] = __shfl_sync(0xffffffffu, y.x, k, 8);
      yoi[k] = __shfl_sync(0xffffffffu, y.y, k, 8);
    }
    float sr0 = cxr, si0 = cxi, sr1 = 0.f, si1 = 0.f;
    CMAC(sr0, si0, cr0.x, ci0.x, yor[0], yoi[0]);
    CMAC(sr1, si1, cr0.y, ci0.y, yor[1], yoi[1]);
    CMAC(sr0, si0, cr0.z, ci0.z, yor[2], yoi[2]);
    CMAC(sr1, si1, cr0.w, ci0.w, yor[3], yoi[3]);
    CMAC(sr0, si0, cr1.x, ci1.x, yor[4], yoi[4]);
    CMAC(sr1, si1, cr1.y, ci1.y, yor[5], yoi[5]);
    CMAC(sr0, si0, cr1.z, ci1.z, yor[6], yoi[6]);
    CMAC(sr1, si1, cr1.w, ci1.w, yor[7], yoi[7]);
    y = make_float2(sr0 + sr1, si0 + si1);
    *op = y;
    op += 512;
  }
}

// ---------------------------------------------------------------------------
extern "C" void kernel_launch(void* const* d_in, const int* in_sizes, int n_in,
                              void* d_out, int out_size)
{
  const float* Are = (const float*)d_in[0];
  const float* Aim = (const float*)d_in[1];
  const float* Xre = (const float*)d_in[2];
  const float* Xim = (const float*)d_in[3];
  float2* out = (float2*)d_out;

  k_fold<<<4 * 128 * 4, 64>>>(Are, Aim, Xre, Xim);         // 2048 CTAs
  k_scan<<<(NSEQ * 8 + 255) / 256, 256>>>();               // 8 CTAs
  k_replay<<<4 * 128 * 4, 128>>>(Are, Aim, Xre, Xim, out); // 2048 CTAs
}

// round 10
// speedup vs baseline: 1.3464x; 1.0505x over previous
#include <cuda_runtime.h>
#include <cuda_bf16.h>
#include <cstdint>

using ull = unsigned long long;

__device__ __forceinline__ ull pk(float lo, float hi) {
  ull r; asm("mov.b64 %0, {%1,%2};" : "=l"(r) : "f"(lo), "f"(hi)); return r;
}
__device__ __forceinline__ void upk(ull v, float& lo, float& hi) {
  asm("mov.b64 {%0,%1}, %2;" : "=f"(lo), "=f"(hi) : "l"(v));
}
__device__ __forceinline__ ull ffma2(ull a, ull b, ull c) {
  ull d; asm("fma.rn.f32x2 %0, %1, %2, %3;" : "=l"(d) : "l"(a), "l"(b), "l"(c)); return d;
}
__device__ __forceinline__ void cpa16(uint32_t dst, const void* src) {
  asm volatile("cp.async.ca.shared.global [%0], [%1], 16;" :: "r"(dst), "l"(src));
}
#define CP_COMMIT() asm volatile("cp.async.commit_group;")
#define CP_WAIT1()  asm volatile("cp.async.wait_group 1;")

// Scalar complex MAC: (sr,si) += (ar,ai)*(br,bi)
#define CMAC(sr, si, ar, ai, br, bi) do { \
  (sr) = fmaf((ar), (br), (sr)); (sr) = fmaf(-(ai), (bi), (sr)); \
  (si) = fmaf((ar), (bi), (si)); (si) = fmaf((ai), (br), (si)); } while (0)

constexpr int Lc = 2048;
constexpr int T = 16;                   // steps per chunk
constexpr int NCHUNK = Lc / T;          // 128
constexpr int NSEQ = 256;               // B*C
constexpr int NUNIT = NSEQ * NCHUNK;    // 32768

__device__ float2 g_M2[NUNIT * 64];     // 16 MB: chunk transition matrices
__device__ float2 g_v2[NUNIT * 8];      // 2 MB: chunk offsets
__device__ float2 g_E2[NUNIT * 8];      // 2 MB: entering states

constexpr int FU_STRIDE = 1232;

// ---------------------------------------------------------------------------
// Kernel 1: fold T steps into (M, v). Same algorithm as R7/R9 (verified);
// only change: reg cap 102 via __launch_bounds__(64,10) for 10 CTAs/SM.
// ---------------------------------------------------------------------------
__global__ __launch_bounds__(64, 10) void k_fold(
    const float* __restrict__ Are, const float* __restrict__ Aim,
    const float* __restrict__ Xre, const float* __restrict__ Xim)
{
  __shared__ __align__(16) char smraw[16 * FU_STRIDE];

  const int tid = threadIdx.x;
  const int u = tid >> 2, h = tid & 3;
  const int bid = blockIdx.x;                 // = ((b*128 + chunk)*4 + cg)
  const int cg = bid & 3;
  const int chunk = (bid >> 2) & 127;
  const int b = bid >> 9;
  const int c = cg * 16 + u;
  const int unit = (b * 64 + c) * NCHUNK + chunk;
  const int t0 = chunk * T;

  const float* aRe = Are + ((size_t)(b * Lc + t0) * 64 + c) * 64;
  const float* aIm = Aim + ((size_t)(b * Lc + t0) * 64 + c) * 64;
  const float* xRe = Xre + ((size_t)(b * Lc + t0) * 64 + c) * 8;
  const float* xIm = Xim + ((size_t)(b * Lc + t0) * 64 + c) * 8;

  char* su = smraw + u * FU_STRIDE;
  const uint32_t suA = (uint32_t)__cvta_generic_to_shared(su);
  ull* vbuf = (ull*)(su + 1152);

  #define STAGE(t, st) do { \
    const float* r_ = aRe + (t) * 4096 + h * 16; \
    const float* i_ = aIm + (t) * 4096 + h * 16; \
    uint32_t d_ = suA + (st) * 512 + h * 64; \
    cpa16(d_, r_); cpa16(d_ + 16, r_ + 4); cpa16(d_ + 32, r_ + 8); cpa16(d_ + 48, r_ + 12); \
    cpa16(d_ + 256, i_); cpa16(d_ + 272, i_ + 4); cpa16(d_ + 288, i_ + 8); cpa16(d_ + 304, i_ + 12); \
    if (h == 2) { const float* x_ = xRe + (t) * 512; uint32_t dx_ = suA + 1024 + (st) * 64; \
      cpa16(dx_, x_); cpa16(dx_ + 16, x_ + 4); } \
    if (h == 3) { const float* x_ = xIm + (t) * 512; uint32_t dx_ = suA + 1024 + (st) * 64 + 32; \
      cpa16(dx_, x_); cpa16(dx_ + 16, x_ + 4); } \
  } while (0)

  STAGE(0, 0); CP_COMMIT();
  STAGE(1, 1); CP_COMMIT();
  CP_WAIT1();
  __syncwarp();

  const int c0 = h, c1 = h + 4;

  ull Mc0[8], Mc1[8];
  {
    const float* sre = (const float*)(su);
    const float* sim = (const float*)(su + 256);
    #pragma unroll
    for (int i = 0; i < 8; i++) {
      Mc0[i] = pk(sre[i * 8 + c0], sim[i * 8 + c0]);
      Mc1[i] = pk(sre[i * 8 + c1], sim[i * 8 + c1]);
    }
    const float* xr = (const float*)(su + 1024);
    const float* xi = xr + 8;
    vbuf[c0] = pk(xr[c0], xi[c0]);
    vbuf[c1] = pk(xr[c1], xi[c1]);
  }
  __syncwarp();

  ull vnew0 = vbuf[c0], vnew1 = vbuf[c1];

  for (int s = 1; s < T; ++s) {
    if (s + 1 < T) STAGE(s + 1, (s + 1) & 1);
    CP_COMMIT();
    CP_WAIT1();
    __syncwarp();

    const char* stg = su + (s & 1) * 512;
    const float* sre = (const float*)(stg);
    const float* sim = (const float*)(stg + 256);

    ull n0[8], n1[8];
    #pragma unroll
    for (int i = 0; i < 8; i++) {
      const float4* rr = (const float4*)(sre + i * 8);
      const float4* ii = (const float4*)(sim + i * 8);
      float4 ra = rr[0], rb = rr[1], ia = ii[0], ib = ii[1];
      ull a10 = 0, a20 = 0, a11 = 0, a21 = 0;
      #define STEPK(RF, IF, K) do { \
        ull dr_ = pk((RF), (RF)); ull di_ = pk((IF), (IF)); \
        a10 = ffma2(dr_, Mc0[K], a10); a20 = ffma2(di_, Mc0[K], a20); \
        a11 = ffma2(dr_, Mc1[K], a11); a21 = ffma2(di_, Mc1[K], a21); } while (0)
      STEPK(ra.x, ia.x, 0); STEPK(ra.y, ia.y, 1);
      STEPK(ra.z, ia.z, 2); STEPK(ra.w, ia.w, 3);
      STEPK(rb.x, ib.x, 4); STEPK(rb.y, ib.y, 5);
      STEPK(rb.z, ib.z, 6); STEPK(rb.w, ib.w, 7);
      #undef STEPK
      float l1, h1, l2, h2;
      upk(a10, l1, h1); upk(a20, l2, h2);
      n0[i] = pk(l1 - h2, h1 + l2);
      upk(a11, l1, h1); upk(a21, l2, h2);
      n1[i] = pk(l1 - h2, h1 + l2);
    }

    {
      const ulonglong2* vb2 = (const ulonglong2*)vbuf;
      ulonglong2 q0 = vb2[0], q1 = vb2[1], q2 = vb2[2], q3 = vb2[3];
      ull vv[8] = {q0.x, q0.y, q1.x, q1.y, q2.x, q2.y, q3.x, q3.y};
      const float* xr = (const float*)(su + 1024 + (s & 1) * 64);
      const float* xi = xr + 8;
      #pragma unroll
      for (int rsel = 0; rsel < 2; rsel++) {
        const int r = rsel ? c1 : c0;
        const float4* rr = (const float4*)(sre + r * 8);
        const float4* ii = (const float4*)(sim + r * 8);
        float4 ra = rr[0], rb = rr[1], ia = ii[0], ib = ii[1];
        ull a1 = pk(xr[r], xi[r]), a2 = 0;
        #define VK(RF, IF, K) do { \
          ull dr_ = pk((RF), (RF)); ull di_ = pk((IF), (IF)); \
          a1 = ffma2(dr_, vv[K], a1); a2 = ffma2(di_, vv[K], a2); } while (0)
        VK(ra.x, ia.x, 0); VK(ra.y, ia.y, 1); VK(ra.z, ia.z, 2); VK(ra.w, ia.w, 3);
        VK(rb.x, ib.x, 4); VK(rb.y, ib.y, 5); VK(rb.z, ib.z, 6); VK(rb.w, ib.w, 7);
        #undef VK
        float l1, h1, l2, h2; upk(a1, l1, h1); upk(a2, l2, h2);
        ull res = pk(l1 - h2, h1 + l2);
        if (rsel) vnew1 = res; else vnew0 = res;
      }
    }

    #pragma unroll
    for (int i = 0; i < 8; i++) { Mc0[i] = n0[i]; Mc1[i] = n1[i]; }
    __syncwarp();
    vbuf[c0] = vnew0; vbuf[c1] = vnew1;
  }

  float2* gm = g_M2 + (size_t)unit * 64;
  #pragma unroll
  for (int i = 0; i < 8; i++) {
    float re, im;
    upk(Mc0[i], re, im); gm[i * 8 + c0] = make_float2(re, im);
    upk(Mc1[i], re, im); gm[i * 8 + c1] = make_float2(re, im);
  }
  {
    float re, im;
    upk(vnew0, re, im); g_v2[unit * 8 + c0] = make_float2(re, im);
    upk(vnew1, re, im); g_v2[unit * 8 + c1] = make_float2(re, im);
  }
  #undef STAGE
}

// ---------------------------------------------------------------------------
// Kernel 2: serial scan over NCHUNK chunk summaries per sequence.
// 4-deep register prefetch ring; now spread over 64 CTAs (4 seqs each)
// so 64 SMs feed the DRAM latency chain instead of 8.
// ---------------------------------------------------------------------------
__global__ void k_scan()
{
  const int gid = blockIdx.x * blockDim.x + threadIdx.x;
  const int seq = gid >> 3, i = gid & 7;
  if (seq >= NSEQ) return;
  float er = 0.f, ei = 0.f;             // state entering chunk 0 is zero

  const float2* mbase = g_M2 + (size_t)(seq * NCHUNK) * 64;
  const float2* vbase = g_v2 + (size_t)(seq * NCHUNK) * 8;
  float2* ebase = g_E2 + (size_t)(seq * NCHUNK) * 8;

  float4 m[4][4];
  float2 vv[4];
  #pragma unroll
  for (int p = 0; p < 4; p++) {
    const float4* mp = (const float4*)(mbase + p * 64 + i * 8);
    m[p][0] = mp[0]; m[p][1] = mp[1]; m[p][2] = mp[2]; m[p][3] = mp[3];
    vv[p] = vbase[p * 8 + i];
  }

  #pragma unroll 4
  for (int ch = 0; ch < NCHUNK; ++ch) {
    const int slot = ch & 3;
    ebase[ch * 8 + i] = make_float2(er, ei);
    const float4 c0 = m[slot][0], c1 = m[slot][1];
    const float4 c2 = m[slot][2], c3 = m[slot][3];
    const float2 cv = vv[slot];
    if (ch + 4 < NCHUNK) {
      const float4* np = (const float4*)(mbase + (ch + 4) * 64 + i * 8);
      m[slot][0] = np[0]; m[slot][1] = np[1];
      m[slot][2] = np[2]; m[slot][3] = np[3];
      vv[slot] = vbase[(ch + 4) * 8 + i];
    }
    float eor[8], eoi[8];
    #pragma unroll
    for (int k = 0; k < 8; k++) {
      eor[k] = __shfl_sync(0xffffffffu, er, k, 8);
      eoi[k] = __shfl_sync(0xffffffffu, ei, k, 8);
    }
    float sr0 = cv.x, si0 = cv.y, sr1 = 0.f, si1 = 0.f;
    CMAC(sr0, si0, c0.x, c0.y, eor[0], eoi[0]);
    CMAC(sr1, si1, c0.z, c0.w, eor[1], eoi[1]);
    CMAC(sr0, si0, c1.x, c1.y, eor[2], eoi[2]);
    CMAC(sr1, si1, c1.z, c1.w, eor[3], eoi[3]);
    CMAC(sr0, si0, c2.x, c2.y, eor[4], eoi[4]);
    CMAC(sr1, si1, c2.z, c2.w, eor[5], eoi[5]);
    CMAC(sr0, si0, c3.x, c3.y, eor[6], eoi[6]);
    CMAC(sr1, si1, c3.z, c3.w, eor[7], eoi[7]);
    er = sr0 + sr1; ei = si0 + si1;
  }
}

// ---------------------------------------------------------------------------
// Kernel 3: replay each chunk from its entering state; write Y.
// 128 threads = 16 units; 8 lanes/unit. The y-broadcast now goes through a
// double-buffered per-unit SMEM slot (1 STS + 1 syncwarp + 4 LDS.128/step)
// instead of 16 width-8 shuffles.
// ---------------------------------------------------------------------------
__global__ __launch_bounds__(128) void k_replay(
    const float* __restrict__ Are, const float* __restrict__ Aim,
    const float* __restrict__ Xre, const float* __restrict__ Xim,
    float2* __restrict__ out)
{
  // [slot][unit][8 rows + 2 pad] -> unit stride 80 B (conflict-free broadcast)
  __shared__ __align__(16) float2 ybuf[2][16][10];

  const int tid = threadIdx.x;
  const int u = tid >> 3, j = tid & 7;
  const int bid = blockIdx.x;                // = ((b*128 + chunk)*4 + cg)
  const int cg = bid & 3;
  const int chunk = (bid >> 2) & 127;
  const int b = bid >> 9;
  const int c = cg * 16 + u;
  const int unit = (b * 64 + c) * NCHUNK + chunk;
  const int t0 = chunk * T;

  const float* arp = Are + ((size_t)(b * Lc + t0) * 64 + c) * 64 + j * 8;
  const float* aip = Aim + ((size_t)(b * Lc + t0) * 64 + c) * 64 + j * 8;
  const float* xrp = Xre + ((size_t)(b * Lc + t0) * 64 + c) * 8 + j;
  const float* xip = Xim + ((size_t)(b * Lc + t0) * 64 + c) * 8 + j;
  float2* op = out + ((size_t)(b * Lc + t0) * 64 + c) * 8 + j;

  float2 y = g_E2[unit * 8 + j];

  float4 r0 = *(const float4*)(arp), r1 = *(const float4*)(arp + 4);
  float4 i0 = *(const float4*)(aip), i1 = *(const float4*)(aip + 4);
  float xr = xrp[0], xi = xip[0];

  #pragma unroll 2
  for (int s = 0; s < T; ++s) {
    ybuf[s & 1][u][j] = y;               // publish state entering step s
    const float4 cr0 = r0, cr1 = r1, ci0 = i0, ci1 = i1;
    const float cxr = xr, cxi = xi;
    if (s < T - 1) {                     // prefetch next step's A,x
      arp += 4096; aip += 4096; xrp += 512; xip += 512;
      r0 = *(const float4*)(arp); r1 = *(const float4*)(arp + 4);
      i0 = *(const float4*)(aip); i1 = *(const float4*)(aip + 4);
      xr = xrp[0]; xi = xip[0];
    }
    __syncwarp();                        // y(s-1) of all lanes visible
    const float4* yb = (const float4*)&ybuf[s & 1][u][0];
    float4 q0 = yb[0], q1 = yb[1], q2 = yb[2], q3 = yb[3];

    float sr0 = cxr, si0 = cxi, sr1 = 0.f, si1 = 0.f;
    CMAC(sr0, si0, cr0.x, ci0.x, q0.x, q0.y);
    CMAC(sr1, si1, cr0.y, ci0.y, q0.z, q0.w);
    CMAC(sr0, si0, cr0.z, ci0.z, q1.x, q1.y);
    CMAC(sr1, si1, cr0.w, ci0.w, q1.z, q1.w);
    CMAC(sr0, si0, cr1.x, ci1.x, q2.x, q2.y);
    CMAC(sr1, si1, cr1.y, ci1.y, q2.z, q2.w);
    CMAC(sr0, si0, cr1.z, ci1.z, q3.x, q3.y);
    CMAC(sr1, si1, cr1.w, ci1.w, q3.z, q3.w);
    y = make_float2(sr0 + sr1, si0 + si1);
    *op = y;                             // unit writes contiguous 64 B
    op += 512;
  }
}

// ---------------------------------------------------------------------------
extern "C" void kernel_launch(void* const* d_in, const int* in_sizes, int n_in,
                              void* d_out, int out_size)
{
  const float* Are = (const float*)d_in[0];
  const float* Aim = (const float*)d_in[1];
  const float* Xre = (const float*)d_in[2];
  const float* Xim = (const float*)d_in[3];
  float2* out = (float2*)d_out;

  k_fold<<<4 * 128 * 4, 64>>>(Are, Aim, Xre, Xim);         // 2048 CTAs
  k_scan<<<64, 32>>>();                                    // 64 CTAs, 4 seq each
  k_replay<<<4 * 128 * 4, 128>>>(Are, Aim, Xre, Xim, out); // 2048 CTAs
}